// round 4
// baseline (speedup 1.0000x reference)
#include <cuda_runtime.h>

// Shapes (fixed by the problem)
#define NB   8
#define CIN  256
#define COUT 256
#define LL   1024
#define VV   25
#define PP   3
#define KWIN 9
#define SPAD 26   // padded row: 26 floats = 104B, 8B-aligned pairs

typedef unsigned long long u64;

// Packed f32x2 ops (sm_100+ PTX; FFMA2 in SASS — 2 FLOPs per FMA-pipe issue)
#define FMA2(d, a, b, c) \
    asm("fma.rn.f32x2 %0, %1, %2, %3;" : "=l"(d) : "l"(a), "l"(b), "l"(c))
#define ADD2(d, a, b) \
    asm("add.rn.f32x2 %0, %1, %2;" : "=l"(d) : "l"(a), "l"(b))
#define PACK2(d, s) \
    asm("mov.b64 %0, {%1, %1};" : "=l"(d) : "f"(s))

// Scratch (device globals: allocation-free rule)
__device__ float  g_s[NB * CIN * LL * VV];     // temporal sliding sums
__device__ float4 g_Wt4[(CIN / 4) * PP * COUT]; // Wt4[k4][o] = w[4k4..4k4+3][o]
__device__ float  g_AeffP[PP * VV * SPAD];      // (A_p * ei), rows padded to 26

// ---------------------------------------------------------------------------
// K0: prep — repack conv_w into float4-over-k; fold edge_importance into A.
// grid <<<768, 256>>>
// ---------------------------------------------------------------------------
__global__ void prep_kernel(const float* __restrict__ conv_w,
                            const float* __restrict__ A1,
                            const float* __restrict__ A2,
                            const float* __restrict__ A3,
                            const float* __restrict__ ei) {
    const int o = blockIdx.x;          // 0..767
    if (threadIdx.x < CIN / 4) {       // k4 = threadIdx.x
        const int k4 = threadIdx.x;
        float4 w = ((const float4*)(conv_w + o * CIN))[k4];
        g_Wt4[k4 * (PP * COUT) + o] = w;
    }
    int i = blockIdx.x * 256 + threadIdx.x;
    if (i < PP * VV * SPAD) {
        int p = i / (VV * SPAD);
        int r = i % (VV * SPAD);
        int v = r / SPAD;
        int w = r % SPAD;
        const float* Ap = (p == 0) ? A1 : ((p == 1) ? A2 : A3);
        g_AeffP[i] = (w < VV) ? Ap[v * VV + w] * ei[p * (VV * VV) + v * VV + w]
                              : 0.f;
    }
}

// ---------------------------------------------------------------------------
// K1: temporal causal 9-tap sliding sum over L.
// ---------------------------------------------------------------------------
__global__ void temporal_kernel(const float* __restrict__ x) {
    int t = blockIdx.x * blockDim.x + threadIdx.x;
    if (t >= NB * CIN * VV) return;
    int v  = t % VV;
    int rc = t / VV;                          // n*CIN + ci
    int base = rc * (LL * VV) + v;

    float run = 0.f;
    #pragma unroll 4
    for (int m = 0; m < LL; ++m) {
        run += x[base + m * VV];
        if (m >= KWIN) run -= x[base + (m - KWIN) * VV];
        g_s[base + m * VV] = run;
    }
}

// ---------------------------------------------------------------------------
// K2: per-(n,m) fused GEMM (768x256x25) + spatial + LN + relu + residual.
// Inner math on packed f32x2 lanes (13 pairs cover V=25 + 1 zero pad).
// ---------------------------------------------------------------------------
__global__ __launch_bounds__(256, 2)
void main_kernel(const float* __restrict__ x,
                 const float* __restrict__ conv_b,
                 const float* __restrict__ ln_gamma,
                 const float* __restrict__ ln_beta,
                 float* __restrict__ out) {
    __shared__ float s_sh[CIN * SPAD];        // 26.6 KB
    __shared__ float a_sh[PP * VV * SPAD];    // 7.8 KB
    __shared__ float red[16];

    const int n = blockIdx.x >> 10;
    const int m = blockIdx.x & 1023;
    const int t = threadIdx.x;

    // load s slice: s[n, t, m, 0..24]; zero the pad lane
    {
        const int sbase = ((n * CIN + t) * LL + m) * VV;
        #pragma unroll
        for (int v = 0; v < VV; ++v) s_sh[t * SPAD + v] = g_s[sbase + v];
        s_sh[t * SPAD + VV] = 0.f;
    }
    for (int i = t; i < PP * VV * SPAD; i += 256) a_sh[i] = g_AeffP[i];
    __syncthreads();

    u64 acc0[13], acc1[13], acc2[13];
    #pragma unroll
    for (int j = 0; j < 13; ++j) { acc0[j] = 0ull; acc1[j] = 0ull; acc2[j] = 0ull; }

    // main GEMM: K = 256 channels, 4 per float4 weight load
    const float4* __restrict__ W4 = g_Wt4;
    for (int k4 = 0; k4 < CIN / 4; ++k4) {
        const float4 w0v = W4[k4 * 768 + t];
        const float4 w1v = W4[k4 * 768 + t + 256];
        const float4 w2v = W4[k4 * 768 + t + 512];
        const u64* __restrict__ sr = (const u64*)&s_sh[(4 * k4) * SPAD];

        #define GSTEP(WA, WB, WC, OFF)                                        \
        do {                                                                  \
            u64 wap, wbp, wcp;                                                \
            PACK2(wap, WA); PACK2(wbp, WB); PACK2(wcp, WC);                   \
            _Pragma("unroll")                                                 \
            for (int j = 0; j < 13; ++j) {                                    \
                const u64 sv = sr[(OFF) + j];                                 \
                FMA2(acc0[j], wap, sv, acc0[j]);                              \
                FMA2(acc1[j], wbp, sv, acc1[j]);                              \
                FMA2(acc2[j], wcp, sv, acc2[j]);                              \
            }                                                                 \
        } while (0)

        GSTEP(w0v.x, w1v.x, w2v.x, 0);
        GSTEP(w0v.y, w1v.y, w2v.y, 13);
        GSTEP(w0v.z, w1v.z, w2v.z, 26);
        GSTEP(w0v.w, w1v.w, w2v.w, 39);
        #undef GSTEP
    }

    // bias: +n_l(m) * b[o] (temporal sum of per-l bias), packed adds
    {
        const float nl = (float)((m + 1 < KWIN) ? (m + 1) : KWIN);
        u64 b0p, b1p, b2p;
        PACK2(b0p, nl * conv_b[t]);
        PACK2(b1p, nl * conv_b[t + 256]);
        PACK2(b2p, nl * conv_b[t + 512]);
        #pragma unroll
        for (int j = 0; j < 13; ++j) {
            ADD2(acc0[j], acc0[j], b0p);
            ADD2(acc1[j], acc1[j], b1p);
            ADD2(acc2[j], acc2[j], b2p);
        }
    }

    // spatial epilogue: ov[w] = sum_p sum_v Y_p[v] * Aeff[p][v][w] (packed)
    u64 ovp[13];
    #pragma unroll
    for (int j = 0; j < 13; ++j) ovp[j] = 0ull;
    #pragma unroll
    for (int v = 0; v < VV; ++v) {
        const float2 p0 = *(const float2*)&acc0[v >> 1];
        const float2 p1 = *(const float2*)&acc1[v >> 1];
        const float2 p2 = *(const float2*)&acc2[v >> 1];
        const float a0 = (v & 1) ? p0.y : p0.x;
        const float a1 = (v & 1) ? p1.y : p1.x;
        const float a2 = (v & 1) ? p2.y : p2.x;
        u64 a0p, a1p, a2p;
        PACK2(a0p, a0); PACK2(a1p, a1); PACK2(a2p, a2);
        const u64* __restrict__ Ar0 = (const u64*)&a_sh[(0 * VV + v) * SPAD];
        const u64* __restrict__ Ar1 = (const u64*)&a_sh[(1 * VV + v) * SPAD];
        const u64* __restrict__ Ar2 = (const u64*)&a_sh[(2 * VV + v) * SPAD];
        #pragma unroll
        for (int j = 0; j < 13; ++j) {
            FMA2(ovp[j], a0p, Ar0[j], ovp[j]);
            FMA2(ovp[j], a1p, Ar1[j], ovp[j]);
            FMA2(ovp[j], a2p, Ar2[j], ovp[j]);
        }
    }

    // LayerNorm over (c=256, w=25) = 6400 elements (pad lane is exactly 0)
    float sm = 0.f, sq = 0.f;
    #pragma unroll
    for (int j = 0; j < 13; ++j) {
        const float2 o2 = *(const float2*)&ovp[j];
        sm += o2.x + o2.y;
        sq = fmaf(o2.x, o2.x, fmaf(o2.y, o2.y, sq));
    }
    #pragma unroll
    for (int off = 16; off > 0; off >>= 1) {
        sm += __shfl_xor_sync(0xFFFFFFFFu, sm, off);
        sq += __shfl_xor_sync(0xFFFFFFFFu, sq, off);
    }
    const int warp = t >> 5;
    if ((t & 31) == 0) { red[warp] = sm; red[8 + warp] = sq; }
    __syncthreads();
    float tsum = 0.f, tsq = 0.f;
    #pragma unroll
    for (int i = 0; i < 8; ++i) { tsum += red[i]; tsq += red[8 + i]; }
    const float mean = tsum * (1.f / 6400.f);
    const float var  = tsq * (1.f / 6400.f) - mean * mean;
    const float rstd = rsqrtf(var + 1e-5f);

    // affine + relu + residual + relu + store
    const int xb = ((n * CIN + t) * LL + m) * VV;
    #pragma unroll
    for (int w = 0; w < VV; ++w) {
        const float2 o2 = *(const float2*)&ovp[w >> 1];
        const float o  = (w & 1) ? o2.y : o2.x;
        const float g  = ln_gamma[t * VV + w];
        const float be = ln_beta[t * VV + w];
        float h = fmaf((o - mean) * rstd, g, be);
        h = fmaxf(h, 0.f);
        const float r = x[xb + w];
        out[xb + w] = fmaxf(h + r, 0.f);
    }
}

// ---------------------------------------------------------------------------
extern "C" void kernel_launch(void* const* d_in, const int* in_sizes, int n_in,
                              void* d_out, int out_size) {
    const float* x      = (const float*)d_in[0];
    const float* A1     = (const float*)d_in[1];
    const float* A2     = (const float*)d_in[2];
    const float* A3     = (const float*)d_in[3];
    const float* conv_w = (const float*)d_in[4];
    const float* conv_b = (const float*)d_in[5];
    const float* gamma  = (const float*)d_in[6];
    const float* beta   = (const float*)d_in[7];
    const float* ei     = (const float*)d_in[8];
    float* out          = (float*)d_out;

    prep_kernel<<<PP * COUT, CIN>>>(conv_w, A1, A2, A3, ei);
    temporal_kernel<<<(NB * CIN * VV + 255) / 256, 256>>>(x);
    main_kernel<<<NB * LL, 256>>>(x, conv_b, gamma, beta, out);
}

// round 6
// speedup vs baseline: 1.2488x; 1.2488x over previous
#include <cuda_runtime.h>
#include <cuda_bf16.h>
#include <cstdint>

// ---------------- problem shapes ----------------
#define NB    8
#define CIN   256
#define LL    1024
#define VV    25
#define PP    3
#define KWIN  9
#define APAD  28

// ---------------- gemm tiling -------------------
// CTA: 256 threads / 8 warps; 2 positions; M=768 (warp: 96 rows = 6 mtiles),
// N=64 (8 ntiles of 8), K=256 (16 ksteps of 16).
#define NWARP 8
#define MT    6
#define NT    8
#define KS    16
#define STR_ST 264              // sT row stride in bf16 elements
#define STR_Y  66               // Y row stride in floats

// smem layout (bytes)
#define SM_STH   0
#define SM_STL   33792          // 64*264*2
#define SM_Y     0              // union with sT (Y written after GEMM)
#define SM_AEFF  202752         // 768*66*4
#define SM_RED   211152
#define SM_TOTAL 211232

// ---------------- device scratch ----------------
__device__ float         g_s[NB*CIN*LL*VV];          // temporal sliding sums
__device__ __nv_bfloat16 g_Wf[2*48*KS*32*8];         // fragment-major W (hi, lo)
__device__ float         g_Aeff[PP*VV*APAD];         // A_p * ei, padded rows
__device__ float         g_bA[256*VV];               // folded bias

// ---------------------------------------------------------------------------
// prep: pack conv_w into m16n8k16 A-fragment layout (bf16 hi/lo planes);
// build Aeff (padded) and folded bias bA.
// grid <<<768, 256>>>: o = blockIdx (W row), k = threadIdx (W col)
// ---------------------------------------------------------------------------
__global__ void prep_kernel(const float* __restrict__ conv_w,
                            const float* __restrict__ A1,
                            const float* __restrict__ A2,
                            const float* __restrict__ A3,
                            const float* __restrict__ ei,
                            const float* __restrict__ conv_b) {
    const int o = blockIdx.x;       // 0..767
    const int k = threadIdx.x;      // 0..255
    {
        float w = conv_w[o*CIN + k];
        __nv_bfloat16 h = __float2bfloat16(w);
        __nv_bfloat16 l = __float2bfloat16(w - __bfloat162float(h));
        const int mt  = o >> 4, r = o & 15;
        const int ks  = k >> 4, kk = k & 15;
        const int reg = ((r >> 3) & 1) | ((kk >> 3) << 1);   // a0..a3
        const int lane = (r & 7) * 4 + ((kk & 7) >> 1);
        const int byt  = kk & 1;
        const size_t off = ((((size_t)mt)*KS + ks)*32 + lane)*8 + reg*2 + byt;
        g_Wf[off] = h;
        g_Wf[(size_t)48*KS*32*8 + off] = l;
    }
    if (blockIdx.x == 0) {
        for (int i = k; i < PP*VV*APAD; i += 256) {
            int p = i/(VV*APAD), rr = i%(VV*APAD), v = rr/APAD, w2 = rr%APAD;
            const float* Ap = (p==0) ? A1 : ((p==1) ? A2 : A3);
            g_Aeff[i] = (w2 < VV) ? Ap[v*VV + w2] * ei[p*VV*VV + v*VV + w2] : 0.f;
        }
    }
    if (blockIdx.x == 1) {
        const int c = k;
        for (int w2 = 0; w2 < VV; ++w2) {
            float acc = 0.f;
            for (int p = 0; p < PP; ++p) {
                const float* Ap = (p==0) ? A1 : ((p==1) ? A2 : A3);
                float cs = 0.f;
                for (int v = 0; v < VV; ++v)
                    cs += Ap[v*VV + w2] * ei[p*VV*VV + v*VV + w2];
                acc += conv_b[p*256 + c] * cs;
            }
            g_bA[c*VV + w2] = acc;
        }
    }
}

// ---------------------------------------------------------------------------
// temporal: causal 9-tap sliding sum over L.
// ---------------------------------------------------------------------------
__global__ void temporal_kernel(const float* __restrict__ x) {
    int t = blockIdx.x * blockDim.x + threadIdx.x;
    if (t >= NB*CIN*VV) return;
    int v  = t % VV;
    int rc = t / VV;
    int base = rc * (LL*VV) + v;
    float run = 0.f;
    #pragma unroll 4
    for (int m = 0; m < LL; ++m) {
        run += x[base + m*VV];
        if (m >= KWIN) run -= x[base + (m - KWIN)*VV];
        g_s[base + m*VV] = run;
    }
}

// ---------------------------------------------------------------------------
__device__ __forceinline__ void mma16816(float c[4], const uint32_t a[4],
                                         const uint32_t b[2]) {
    asm volatile(
        "mma.sync.aligned.m16n8k16.row.col.f32.bf16.bf16.f32 "
        "{%0,%1,%2,%3}, {%4,%5,%6,%7}, {%8,%9}, {%0,%1,%2,%3};"
        : "+f"(c[0]), "+f"(c[1]), "+f"(c[2]), "+f"(c[3])
        : "r"(a[0]), "r"(a[1]), "r"(a[2]), "r"(a[3]), "r"(b[0]), "r"(b[1]));
}

// ---------------------------------------------------------------------------
// fused mma.sync GEMM (bf16 3-pass) + spatial + LN + residual.
// One CTA = 2 positions.
// ---------------------------------------------------------------------------
__global__ __launch_bounds__(256, 1)
void gemm_kernel(const float* __restrict__ x,
                 const float* __restrict__ ln_gamma,
                 const float* __restrict__ ln_beta,
                 float* __restrict__ out) {
    extern __shared__ char smem[];
    __nv_bfloat16* sth = (__nv_bfloat16*)(smem + SM_STH);
    __nv_bfloat16* stl = (__nv_bfloat16*)(smem + SM_STL);
    float*         Ysh = (float*)(smem + SM_Y);
    float*         Ae  = (float*)(smem + SM_AEFF);
    float*         red = (float*)(smem + SM_RED);

    const int t = threadIdx.x, wid = t >> 5, lane = t & 31;
    const int n  = blockIdx.x >> 9;
    const int m0 = (blockIdx.x & 511) * 2;

    // load Aeff (separate region, persists through epilogue)
    for (int i = t; i < PP*VV*APAD; i += 256) Ae[i] = g_Aeff[i];

    // zero sT (pads must be 0-safe), then stage s -> bf16 hi/lo transposed
    {
        uint4* z4 = (uint4*)smem;
        for (int i = t; i < (2*64*STR_ST*2)/16; i += 256)
            z4[i] = make_uint4(0, 0, 0, 0);
    }
    __syncthreads();
    for (int idx = t; idx < 256*2*VV; idx += 256) {
        int ci = idx / (2*VV), q = idx % (2*VV);
        int pos = q / VV, v = q % VV;
        float sv = g_s[((n*CIN + ci)*LL + (m0 + pos))*VV + v];
        __nv_bfloat16 h = __float2bfloat16(sv);
        __nv_bfloat16 l = __float2bfloat16(sv - __bfloat162float(h));
        int row = pos*32 + v;
        sth[row*STR_ST + ci] = h;
        stl[row*STR_ST + ci] = l;
    }
    __syncthreads();

    // -------------------- GEMM --------------------
    float acc[MT][NT][4];
    #pragma unroll
    for (int mt = 0; mt < MT; ++mt)
        #pragma unroll
        for (int nt = 0; nt < NT; ++nt)
            #pragma unroll
            for (int r = 0; r < 4; ++r) acc[mt][nt][r] = 0.f;

    const uint4* __restrict__ Wf4 = (const uint4*)g_Wf;
    const int mbase = wid * MT;                  // warp's first mtile (global)
    const int brow  = (lane >> 2);               // n within ntile
    const int bcol  = 2 * (lane & 3);            // k-pair within kstep

    for (int ks = 0; ks < KS; ++ks) {
        // B fragments (all 8 ntiles, hi+lo): conflict-free b32 LDS
        uint32_t bh[NT][2], bl[NT][2];
        #pragma unroll
        for (int nt = 0; nt < NT; ++nt) {
            const int o = (nt*8 + brow)*STR_ST + ks*16 + bcol;
            bh[nt][0] = *(const uint32_t*)(sth + o);
            bh[nt][1] = *(const uint32_t*)(sth + o + 8);
            bl[nt][0] = *(const uint32_t*)(stl + o);
            bl[nt][1] = *(const uint32_t*)(stl + o + 8);
        }
        // A fragments streamed from gmem (L2-resident), 1-deep prefetch
        uint4 ah = Wf4[((size_t)(mbase + 0)*KS + ks)*32 + lane];
        uint4 al = Wf4[((size_t)(48 + mbase + 0)*KS + ks)*32 + lane];
        #pragma unroll
        for (int mt = 0; mt < MT; ++mt) {
            uint4 ah_n, al_n;
            if (mt < MT-1) {
                ah_n = Wf4[((size_t)(mbase + mt + 1)*KS + ks)*32 + lane];
                al_n = Wf4[((size_t)(48 + mbase + mt + 1)*KS + ks)*32 + lane];
            }
            const uint32_t* ahr = (const uint32_t*)&ah;
            const uint32_t* alr = (const uint32_t*)&al;
            #pragma unroll
            for (int nt = 0; nt < NT; ++nt) {
                mma16816(acc[mt][nt], ahr, bh[nt]);   // hh
                mma16816(acc[mt][nt], ahr, bl[nt]);   // hl
                mma16816(acc[mt][nt], alr, bh[nt]);   // lh
            }
            if (mt < MT-1) { ah = ah_n; al = al_n; }
        }
    }
    __syncthreads();   // sT dead; Y region reusable

    // -------------------- STS Y --------------------
    #pragma unroll
    for (int mt = 0; mt < MT; ++mt) {
        const int row0 = wid*96 + mt*16 + (lane >> 2);
        #pragma unroll
        for (int nt = 0; nt < NT; ++nt) {
            const int col = nt*8 + 2*(lane & 3);
            *(float2*)&Ysh[row0*STR_Y + col] =
                make_float2(acc[mt][nt][0], acc[mt][nt][1]);
            *(float2*)&Ysh[(row0+8)*STR_Y + col] =
                make_float2(acc[mt][nt][2], acc[mt][nt][3]);
        }
    }
    __syncthreads();

    // -------------------- epilogue: spatial + LN + residual --------------------
    const int c = t;
    for (int pos = 0; pos < 2; ++pos) {
        const int m = m0 + pos;
        float z[APAD];
        #pragma unroll
        for (int w = 0; w < APAD; ++w) z[w] = 0.f;

        #pragma unroll
        for (int p = 0; p < PP; ++p) {
            const float* yrow = &Ysh[(p*256 + c)*STR_Y + pos*32];
            const float* arow = Ae + p*VV*APAD;
            #pragma unroll
            for (int v = 0; v < VV; ++v) {
                const float yv = yrow[v];
                const float4* a4 = (const float4*)(arow + v*APAD);
                #pragma unroll
                for (int j = 0; j < 7; ++j) {
                    float4 a = a4[j];
                    z[4*j+0] = fmaf(yv, a.x, z[4*j+0]);
                    z[4*j+1] = fmaf(yv, a.y, z[4*j+1]);
                    z[4*j+2] = fmaf(yv, a.z, z[4*j+2]);
                    z[4*j+3] = fmaf(yv, a.w, z[4*j+3]);
                }
            }
        }
        const float nl = (float)((m + 1 < KWIN) ? (m + 1) : KWIN);
        float sm_ = 0.f, sq_ = 0.f;
        #pragma unroll
        for (int w = 0; w < VV; ++w) {
            z[w] = fmaf(nl, g_bA[c*VV + w], z[w]);
            sm_ += z[w];
            sq_  = fmaf(z[w], z[w], sq_);
        }
        #pragma unroll
        for (int off = 16; off > 0; off >>= 1) {
            sm_ += __shfl_xor_sync(0xFFFFFFFFu, sm_, off);
            sq_ += __shfl_xor_sync(0xFFFFFFFFu, sq_, off);
        }
        if (lane == 0) { red[wid] = sm_; red[8 + wid] = sq_; }
        __syncthreads();
        float ts = 0.f, tq = 0.f;
        #pragma unroll
        for (int i = 0; i < 8; ++i) { ts += red[i]; tq += red[8 + i]; }
        const float mean = ts * (1.f / 6400.f);
        const float var  = tq * (1.f / 6400.f) - mean*mean;
        const float rstd = rsqrtf(var + 1e-5f);

        const int ib = ((n*CIN + c)*LL + m)*VV;
        #pragma unroll
        for (int w = 0; w < VV; ++w) {
            float h = fmaf((z[w] - mean)*rstd, ln_gamma[c*VV + w], ln_beta[c*VV + w]);
            h = fmaxf(h, 0.f);
            out[ib + w] = fmaxf(h + x[ib + w], 0.f);
        }
        __syncthreads();
    }
}

// ---------------------------------------------------------------------------
extern "C" void kernel_launch(void* const* d_in, const int* in_sizes, int n_in,
                              void* d_out, int out_size) {
    const float* x      = (const float*)d_in[0];
    const float* A1     = (const float*)d_in[1];
    const float* A2     = (const float*)d_in[2];
    const float* A3     = (const float*)d_in[3];
    const float* conv_w = (const float*)d_in[4];
    const float* conv_b = (const float*)d_in[5];
    const float* gamma  = (const float*)d_in[6];
    const float* beta   = (const float*)d_in[7];
    const float* ei     = (const float*)d_in[8];
    float* out          = (float*)d_out;

    cudaFuncSetAttribute(gemm_kernel,
                         cudaFuncAttributeMaxDynamicSharedMemorySize, SM_TOTAL);

    prep_kernel<<<768, 256>>>(conv_w, A1, A2, A3, ei, conv_b);
    temporal_kernel<<<(NB*CIN*VV + 255) / 256, 256>>>(x);
    gemm_kernel<<<NB * (LL/2), 256, SM_TOTAL>>>(x, gamma, beta, out);
}

// round 9
// speedup vs baseline: 1.7008x; 1.3619x over previous
#include <cuda_runtime.h>
#include <cuda_bf16.h>
#include <cstdint>

// ---------------- problem shapes ----------------
#define NB    8
#define CIN   256
#define LL    1024
#define VV    25
#define PP    3
#define KWIN  9
#define APAD  28

// ---------------- gemm tiling -------------------
// CTA: 512 threads / 16 warps; 2 positions packed (cols = pos*25+v, 50 valid).
// M=768 (warp: 48 rows = 3 mtiles), N=56 (7 ntiles of 8), K=256 (16 ksteps).
#define MT    3
#define NT    7
#define KS    16
#define STR_ST 264              // sT row stride in bf16 elements
#define STR_Y  58               // Y row stride in floats (even: float2-safe; mod32=26)

// smem layout (bytes)
#define SM_STH   0
#define SM_STL   33792          // 64*264*2
#define SM_Y     0              // union with sT (written after GEMM)
#define SM_AEFF  178176         // 768*58*4
#define SM_RED   186576         // + 3*25*28*4 = 8400
#define SM_TOTAL 186752

// ---------------- device scratch ----------------
__device__ float         g_s[NB*CIN*LL*VV];          // temporal sliding sums
__device__ __nv_bfloat16 g_Wf[2*48*KS*32*8];         // fragment-major W (hi, lo)
__device__ float         g_Aeff[PP*VV*APAD];         // A_p * ei, padded rows
__device__ float         g_bA[256*VV];               // folded bias

// ---------------------------------------------------------------------------
// prep: pack conv_w into m16n8k16 A-fragment layout (bf16 hi/lo planes);
// build Aeff (padded) and folded bias bA.
// ---------------------------------------------------------------------------
__global__ void prep_kernel(const float* __restrict__ conv_w,
                            const float* __restrict__ A1,
                            const float* __restrict__ A2,
                            const float* __restrict__ A3,
                            const float* __restrict__ ei,
                            const float* __restrict__ conv_b) {
    const int o = blockIdx.x;       // 0..767
    const int k = threadIdx.x;      // 0..255
    {
        float w = conv_w[o*CIN + k];
        __nv_bfloat16 h = __float2bfloat16(w);
        __nv_bfloat16 l = __float2bfloat16(w - __bfloat162float(h));
        const int mt  = o >> 4, r = o & 15;
        const int ks  = k >> 4, kk = k & 15;
        const int reg = ((r >> 3) & 1) | ((kk >> 3) << 1);   // a0..a3
        const int lane = (r & 7) * 4 + ((kk & 7) >> 1);
        const int byt  = kk & 1;
        const size_t off = ((((size_t)mt)*KS + ks)*32 + lane)*8 + reg*2 + byt;
        g_Wf[off] = h;
        g_Wf[(size_t)48*KS*32*8 + off] = l;
    }
    if (blockIdx.x == 0) {
        for (int i = k; i < PP*VV*APAD; i += 256) {
            int p = i/(VV*APAD), rr = i%(VV*APAD), v = rr/APAD, w2 = rr%APAD;
            const float* Ap = (p==0) ? A1 : ((p==1) ? A2 : A3);
            g_Aeff[i] = (w2 < VV) ? Ap[v*VV + w2] * ei[p*VV*VV + v*VV + w2] : 0.f;
        }
    }
    if (blockIdx.x == 1) {
        const int c = k;
        for (int w2 = 0; w2 < VV; ++w2) {
            float acc = 0.f;
            for (int p = 0; p < PP; ++p) {
                const float* Ap = (p==0) ? A1 : ((p==1) ? A2 : A3);
                float cs = 0.f;
                for (int v = 0; v < VV; ++v)
                    cs += Ap[v*VV + w2] * ei[p*VV*VV + v*VV + w2];
                acc += conv_b[p*256 + c] * cs;
            }
            g_bA[c*VV + w2] = acc;
        }
    }
}

// ---------------------------------------------------------------------------
// temporal: causal 9-tap sliding sum over L.
// ---------------------------------------------------------------------------
__global__ void temporal_kernel(const float* __restrict__ x) {
    int t = blockIdx.x * blockDim.x + threadIdx.x;
    if (t >= NB*CIN*VV) return;
    int v  = t % VV;
    int rc = t / VV;
    int base = rc * (LL*VV) + v;
    float run = 0.f;
    #pragma unroll 4
    for (int m = 0; m < LL; ++m) {
        run += x[base + m*VV];
        if (m >= KWIN) run -= x[base + (m - KWIN)*VV];
        g_s[base + m*VV] = run;
    }
}

// ---------------------------------------------------------------------------
__device__ __forceinline__ void mma16816(float c[4], const uint32_t a[4],
                                         const uint32_t b[2]) {
    asm volatile(
        "mma.sync.aligned.m16n8k16.row.col.f32.bf16.bf16.f32 "
        "{%0,%1,%2,%3}, {%4,%5,%6,%7}, {%8,%9}, {%0,%1,%2,%3};"
        : "+f"(c[0]), "+f"(c[1]), "+f"(c[2]), "+f"(c[3])
        : "r"(a[0]), "r"(a[1]), "r"(a[2]), "r"(a[3]), "r"(b[0]), "r"(b[1]));
}

// ---------------------------------------------------------------------------
// fused mma.sync GEMM (bf16 3-pass hi/lo) + spatial + LN + residual.
// One CTA = 2 positions; 512 threads.
// ---------------------------------------------------------------------------
__global__ __launch_bounds__(512, 1)
void gemm_kernel(const float* __restrict__ x,
                 const float* __restrict__ ln_gamma,
                 const float* __restrict__ ln_beta,
                 float* __restrict__ out) {
    extern __shared__ char smem[];
    __nv_bfloat16* sth = (__nv_bfloat16*)(smem + SM_STH);
    __nv_bfloat16* stl = (__nv_bfloat16*)(smem + SM_STL);
    float*         Ysh = (float*)(smem + SM_Y);
    float*         Ae  = (float*)(smem + SM_AEFF);
    float*         red = (float*)(smem + SM_RED);

    const int t = threadIdx.x, wid = t >> 5, lane = t & 31;
    const int n  = blockIdx.x >> 9;
    const int m0 = (blockIdx.x & 511) * 2;

    // Aeff (separate region, persists through epilogue)
    for (int i = t; i < PP*VV*APAD; i += 512) Ae[i] = g_Aeff[i];

    // zero sT (row pad must be benign), then stage s -> bf16 hi/lo transposed
    {
        uint4* z4 = (uint4*)smem;
        for (int i = t; i < (2*64*STR_ST*2)/16; i += 512)
            z4[i] = make_uint4(0, 0, 0, 0);
    }
    __syncthreads();
    for (int idx = t; idx < 256*2*VV; idx += 512) {
        int ci = idx / (2*VV), q = idx % (2*VV);
        int pos = q / VV, v = q % VV;
        float sv = g_s[((n*CIN + ci)*LL + (m0 + pos))*VV + v];
        __nv_bfloat16 h = __float2bfloat16(sv);
        __nv_bfloat16 l = __float2bfloat16(sv - __bfloat162float(h));
        int row = pos*VV + v;                    // packed: 0..49
        sth[row*STR_ST + ci] = h;
        stl[row*STR_ST + ci] = l;
    }
    __syncthreads();

    // -------------------- GEMM --------------------
    float acc[MT][NT][4];
    #pragma unroll
    for (int mt = 0; mt < MT; ++mt)
        #pragma unroll
        for (int nt = 0; nt < NT; ++nt)
            #pragma unroll
            for (int r = 0; r < 4; ++r) acc[mt][nt][r] = 0.f;

    const uint4* __restrict__ Wf4 = (const uint4*)g_Wf;
    const int mbase = wid * MT;                  // warp's first mtile (0..45)
    const int brow  = (lane >> 2);
    const int bcol  = 2 * (lane & 3);

    for (int ks = 0; ks < KS; ++ks) {
        uint32_t bf[NT][2];
        // ---- load B hi ----
        #pragma unroll
        for (int nt = 0; nt < NT; ++nt) {
            const int o = (nt*8 + brow)*STR_ST + ks*16 + bcol;
            bf[nt][0] = *(const uint32_t*)(sth + o);
            bf[nt][1] = *(const uint32_t*)(sth + o + 8);
        }
        // hh pass (A hi), 1-deep prefetch
        {
            uint4 a = Wf4[((size_t)(mbase)*KS + ks)*32 + lane];
            #pragma unroll
            for (int mt = 0; mt < MT; ++mt) {
                uint4 an;
                if (mt < MT-1) an = Wf4[((size_t)(mbase+mt+1)*KS + ks)*32 + lane];
                const uint32_t* ar = (const uint32_t*)&a;
                #pragma unroll
                for (int nt = 0; nt < NT; ++nt) mma16816(acc[mt][nt], ar, bf[nt]);
                if (mt < MT-1) a = an;
            }
        }
        // lh pass (A lo)
        {
            uint4 a = Wf4[((size_t)(48+mbase)*KS + ks)*32 + lane];
            #pragma unroll
            for (int mt = 0; mt < MT; ++mt) {
                uint4 an;
                if (mt < MT-1) an = Wf4[((size_t)(48+mbase+mt+1)*KS + ks)*32 + lane];
                const uint32_t* ar = (const uint32_t*)&a;
                #pragma unroll
                for (int nt = 0; nt < NT; ++nt) mma16816(acc[mt][nt], ar, bf[nt]);
                if (mt < MT-1) a = an;
            }
        }
        // ---- load B lo (overwrite) ----
        #pragma unroll
        for (int nt = 0; nt < NT; ++nt) {
            const int o = (nt*8 + brow)*STR_ST + ks*16 + bcol;
            bf[nt][0] = *(const uint32_t*)(stl + o);
            bf[nt][1] = *(const uint32_t*)(stl + o + 8);
        }
        // hl pass (A hi again; L1-hot)
        {
            uint4 a = Wf4[((size_t)(mbase)*KS + ks)*32 + lane];
            #pragma unroll
            for (int mt = 0; mt < MT; ++mt) {
                uint4 an;
                if (mt < MT-1) an = Wf4[((size_t)(mbase+mt+1)*KS + ks)*32 + lane];
                const uint32_t* ar = (const uint32_t*)&a;
                #pragma unroll
                for (int nt = 0; nt < NT; ++nt) mma16816(acc[mt][nt], ar, bf[nt]);
                if (mt < MT-1) a = an;
            }
        }
    }
    __syncthreads();   // sT dead; Y region reusable

    // -------------------- STS Y --------------------
    #pragma unroll
    for (int mt = 0; mt < MT; ++mt) {
        const int row0 = wid*48 + mt*16 + (lane >> 2);
        #pragma unroll
        for (int nt = 0; nt < NT; ++nt) {
            const int col = nt*8 + 2*(lane & 3);
            *(float2*)&Ysh[row0*STR_Y + col] =
                make_float2(acc[mt][nt][0], acc[mt][nt][1]);
            *(float2*)&Ysh[(row0+8)*STR_Y + col] =
                make_float2(acc[mt][nt][2], acc[mt][nt][3]);
        }
    }
    __syncthreads();

    // ---------- epilogue: spatial + LN + residual (both positions at once) ----
    const int pos = t >> 8;          // warps 0-7 -> pos 0, warps 8-15 -> pos 1
    const int c   = t & 255;
    const int m   = m0 + pos;

    float z[APAD];
    #pragma unroll
    for (int w = 0; w < APAD; ++w) z[w] = 0.f;

    #pragma unroll
    for (int p = 0; p < PP; ++p) {
        const float* yrow = &Ysh[(p*256 + c)*STR_Y + pos*VV];
        const float* arow = Ae + p*VV*APAD;
        #pragma unroll
        for (int v = 0; v < VV; ++v) {
            const float yv = yrow[v];
            const float4* a4 = (const float4*)(arow + v*APAD);
            #pragma unroll
            for (int j = 0; j < 7; ++j) {
                float4 a = a4[j];
                z[4*j+0] = fmaf(yv, a.x, z[4*j+0]);
                z[4*j+1] = fmaf(yv, a.y, z[4*j+1]);
                z[4*j+2] = fmaf(yv, a.z, z[4*j+2]);
                z[4*j+3] = fmaf(yv, a.w, z[4*j+3]);
            }
        }
    }
    const float nl = (float)((m + 1 < KWIN) ? (m + 1) : KWIN);
    float sm_ = 0.f, sq_ = 0.f;
    #pragma unroll
    for (int w = 0; w < VV; ++w) {
        z[w] = fmaf(nl, g_bA[c*VV + w], z[w]);
        sm_ += z[w];
        sq_  = fmaf(z[w], z[w], sq_);
    }
    #pragma unroll
    for (int off = 16; off > 0; off >>= 1) {
        sm_ += __shfl_xor_sync(0xFFFFFFFFu, sm_, off);
        sq_ += __shfl_xor_sync(0xFFFFFFFFu, sq_, off);
    }
    if (lane == 0) { red[wid] = sm_; red[16 + wid] = sq_; }
    __syncthreads();
    float ts = 0.f, tq = 0.f;
    #pragma unroll
    for (int i = 0; i < 8; ++i) { ts += red[pos*8 + i]; tq += red[16 + pos*8 + i]; }
    const float mean = ts * (1.f / 6400.f);
    const float var  = tq * (1.f / 6400.f) - mean*mean;
    const float rstd = rsqrtf(var + 1e-5f);

    const int ib = ((n*CIN + c)*LL + m)*VV;
    #pragma unroll
    for (int w = 0; w < VV; ++w) {
        float h = fmaf((z[w] - mean)*rstd, ln_gamma[c*VV + w], ln_beta[c*VV + w]);
        h = fmaxf(h, 0.f);
        out[ib + w] = fmaxf(h + x[ib + w], 0.f);
    }
}

// ---------------------------------------------------------------------------
extern "C" void kernel_launch(void* const* d_in, const int* in_sizes, int n_in,
                              void* d_out, int out_size) {
    const float* x      = (const float*)d_in[0];
    const float* A1     = (const float*)d_in[1];
    const float* A2     = (const float*)d_in[2];
    const float* A3     = (const float*)d_in[3];
    const float* conv_w = (const float*)d_in[4];
    const float* conv_b = (const float*)d_in[5];
    const float* gamma  = (const float*)d_in[6];
    const float* beta   = (const float*)d_in[7];
    const float* ei     = (const float*)d_in[8];
    float* out          = (float*)d_out;

    cudaFuncSetAttribute(gemm_kernel,
                         cudaFuncAttributeMaxDynamicSharedMemorySize, SM_TOTAL);

    prep_kernel<<<768, 256>>>(conv_w, A1, A2, A3, ei, conv_b);
    temporal_kernel<<<(NB*CIN*VV + 255) / 256, 256>>>(x);
    gemm_kernel<<<NB * (LL/2), 512, SM_TOTAL>>>(x, gamma, beta, out);
}